// round 11
// baseline (speedup 1.0000x reference)
#include <cuda_runtime.h>
#include <cuda_fp16.h>
#include <cstdint>
#include <cstring>
#include <math.h>

#define NN 50000
#define EE 600000
#define HH 128
#define SP 132          // pk kernel padded stride (floats)
#define NPT 782         // ceil(NN/64) node tiles
#define NT 4688         // ceil(EE/128) edge tiles

// ---- gemm smem byte offsets ----
#define GOFF_WG   0          // 128*136 half = 34816
#define GOFF_WR   34816
#define GOFF_B0H  69632
#define GOFF_B0E  104448
#define GOFF_B1H  139264
#define GOFF_B1E  174080
#define GSMEM     208896

// Scratch (__device__ globals: alloc-free rule)
__device__ __align__(16) float  g_Pi[NN * HH];
__device__ __align__(16) float  g_Pj[NN * HH];
__device__ __align__(16) float  g_Wcomb[10 * HH];
__device__ __align__(16) __half g_H16[(size_t)EE * HH];
__device__ __align__(16) __half g_EA16[(size_t)EE * HH];

__device__ __forceinline__ float sigmoidf_(float x) {
    return 1.0f / (1.0f + __expf(-x));
}
__device__ __forceinline__ uint32_t h2u(__half2 v) {
    uint32_t r;
    memcpy(&r, &v, 4);
    return r;
}
__device__ __forceinline__ unsigned f2tf32(float x) {
    unsigned r;
    asm("cvt.rna.tf32.f32 %0, %1;" : "=r"(r) : "f"(x));
    return r;
}
__device__ __forceinline__ uint32_t smem_u32(const void* smem_ptr) {
    uint32_t addr;
    asm("{ .reg .u64 tmp; cvta.to.shared.u64 tmp, %1; cvt.u32.u64 %0, tmp; }"
        : "=r"(addr) : "l"(smem_ptr));
    return addr;
}
__device__ __forceinline__ void mma_tf32(float* d, unsigned a0, unsigned a1,
                                         unsigned a2, unsigned a3,
                                         unsigned b0, unsigned b1) {
    asm volatile(
        "mma.sync.aligned.m16n8k8.row.col.f32.tf32.tf32.f32 "
        "{%0,%1,%2,%3}, {%4,%5,%6,%7}, {%8,%9}, {%0,%1,%2,%3};\n"
        : "+f"(d[0]), "+f"(d[1]), "+f"(d[2]), "+f"(d[3])
        : "r"(a0), "r"(a1), "r"(a2), "r"(a3), "r"(b0), "r"(b1));
}
__device__ __forceinline__ void mma_f16(float* d, uint32_t a0, uint32_t a1,
                                        uint32_t a2, uint32_t a3,
                                        uint32_t b0, uint32_t b1) {
    asm volatile(
        "mma.sync.aligned.m16n8k16.row.col.f32.f16.f16.f32 "
        "{%0,%1,%2,%3}, {%4,%5,%6,%7}, {%8,%9}, {%0,%1,%2,%3};\n"
        : "+f"(d[0]), "+f"(d[1]), "+f"(d[2]), "+f"(d[3])
        : "r"(a0), "r"(a1), "r"(a2), "r"(a3), "r"(b0), "r"(b1));
}

#define CP_ASYNC_16(dst_u32, src_ptr) \
    asm volatile("cp.async.cg.shared.global [%0], [%1], 16;" \
                 :: "r"(dst_u32), "l"(src_ptr) : "memory")
#define CP_COMMIT() asm volatile("cp.async.commit_group;" ::: "memory")
#define CP_WAIT(n)  asm volatile("cp.async.wait_group %0;" :: "n"(n) : "memory")

// ---------------------------------------------------------------------------
// Setup kernel: wcomb (blocks 0-9) + P precompute (tf32 mma).
// PERSISTENT: 148 CTAs loop over node tiles; weights staged once per CTA.
// ---------------------------------------------------------------------------
__global__ __launch_bounds__(256, 1) void pk_kernel(const float* __restrict__ Ei,
                                                    const float* __restrict__ Ej,
                                                    const float* __restrict__ Wsem,
                                                    const float* __restrict__ Wgeo,
                                                    const float* __restrict__ Wpair) {
    extern __shared__ float sm[];
    float* sWt = sm;
    float* sWb = sWt + 128 * SP;
    float* sAi = sWb + 128 * SP;
    float* sAj = sAi + 64 * SP;

    int tid = threadIdx.x;
    int lane = tid & 31;
    int w = tid >> 5;

    if (blockIdx.x < 10 && tid < 128) {
        int c = tid;
        int d = blockIdx.x;
        int dd = d % 5;
        const float* wp = Wpair + (d / 5) * 128 * HH;
        float acc = 0.0f;
#pragma unroll 16
        for (int m = 0; m < 128; m++)
            acc = fmaf(Wgeo[dd * HH + m], wp[m * HH + c], acc);
        g_Wcomb[d * HH + c] = acc;
    }

    // stage weights once per CTA
    for (int i = tid; i < 4096; i += 256) {
        int k = i >> 5, c4 = i & 31;
        float4 t = ((const float4*)Wsem)[i];
        float4 b = ((const float4*)(Wsem + 128 * HH))[i];
        *(uint4*)&sWt[k * SP + c4 * 4] =
            make_uint4(f2tf32(t.x), f2tf32(t.y), f2tf32(t.z), f2tf32(t.w));
        *(uint4*)&sWb[k * SP + c4 * 4] =
            make_uint4(f2tf32(b.x), f2tf32(b.y), f2tf32(b.z), f2tf32(b.w));
    }

    const float* A = (w < 4) ? sAi : sAj;
    const float* W = (w < 4) ? sWt : sWb;
    int nb = (w & 3) * 32;
    int gid = lane >> 2, tig = lane & 3;

    for (int t = blockIdx.x; t < NPT; t += (int)gridDim.x) {
        int base = t * 64;
        __syncthreads();   // prior iteration's sA reads done before overwrite
        for (int i = tid; i < 2048; i += 256) {
            int r = i >> 5, c4 = i & 31;
            int row = base + r;
            float4 v = make_float4(0.f, 0.f, 0.f, 0.f);
            float4 u = make_float4(0.f, 0.f, 0.f, 0.f);
            if (row < NN) {
                v = ((const float4*)Ei)[row * 32 + c4];
                u = ((const float4*)Ej)[row * 32 + c4];
            }
            *(uint4*)&sAi[r * SP + c4 * 4] =
                make_uint4(f2tf32(v.x), f2tf32(v.y), f2tf32(v.z), f2tf32(v.w));
            *(uint4*)&sAj[r * SP + c4 * 4] =
                make_uint4(f2tf32(u.x), f2tf32(u.y), f2tf32(u.z), f2tf32(u.w));
        }
        __syncthreads();

        float acc[4][4][4];
#pragma unroll
        for (int mt = 0; mt < 4; mt++)
#pragma unroll
            for (int nt = 0; nt < 4; nt++)
#pragma unroll
                for (int q = 0; q < 4; q++) { acc[mt][nt][q] = 0.f; }

#pragma unroll
        for (int kt = 0; kt < 16; kt++) {
            int k0 = kt * 8;
            unsigned b[4][2];
#pragma unroll
            for (int nt = 0; nt < 4; nt++) {
                int n = nb + nt * 8 + gid;
                b[nt][0] = __float_as_uint(W[(k0 + tig) * SP + n]);
                b[nt][1] = __float_as_uint(W[(k0 + 4 + tig) * SP + n]);
            }
#pragma unroll
            for (int mt = 0; mt < 4; mt++) {
                int m = mt * 16;
                unsigned a0 = __float_as_uint(A[(m + gid) * SP + k0 + tig]);
                unsigned a1 = __float_as_uint(A[(m + gid + 8) * SP + k0 + tig]);
                unsigned a2 = __float_as_uint(A[(m + gid) * SP + k0 + tig + 4]);
                unsigned a3 = __float_as_uint(A[(m + gid + 8) * SP + k0 + tig + 4]);
#pragma unroll
                for (int nt = 0; nt < 4; nt++)
                    mma_tf32(acc[mt][nt], a0, a1, a2, a3, b[nt][0], b[nt][1]);
            }
        }

        float* G = (w < 4) ? g_Pi : g_Pj;
#pragma unroll
        for (int mt = 0; mt < 4; mt++)
#pragma unroll
            for (int nt = 0; nt < 4; nt++) {
                int row0 = base + mt * 16 + gid;
                int col = nb + nt * 8 + 2 * tig;
                if (row0 < NN)
                    *(float2*)&G[(size_t)row0 * HH + col] =
                        make_float2(acc[mt][nt][0], acc[mt][nt][1]);
                int row1 = row0 + 8;
                if (row1 < NN)
                    *(float2*)&G[(size_t)row1 * HH + col] =
                        make_float2(acc[mt][nt][2], acc[mt][nt][3]);
            }
    }
}

// ---------------------------------------------------------------------------
// Phase A kernel: geometry + gate + LayerNorm. 256 threads, 32 edges/CTA,
// one warp per edge (4 edges). ALL loads batched up-front for max MLP:
// 8 index loads, then 20 dependent loads in flight, then compute.
// ---------------------------------------------------------------------------
__global__ __launch_bounds__(256, 2) void phaseA_kernel(
    const float* __restrict__ pos_i, const float* __restrict__ pos_j,
    const float* __restrict__ hd_i, const float* __restrict__ hd_j,
    const int* __restrict__ eidx, const float* __restrict__ edge_attr,
    const float* __restrict__ b_sem, const float* __restrict__ gamma,
    const float* __restrict__ beta) {
    __shared__ float sWc[10 * HH];

    int tid = threadIdx.x;
    int lane = tid & 31;
    int w = tid >> 5;
    int col = lane * 4;
    int base = blockIdx.x * 32;

    for (int i = tid; i < 1280; i += 256) sWc[i] = g_Wcomb[i];
    __syncthreads();

    float4 bs = *(const float4*)&b_sem[col];
    float4 gm = *(const float4*)&gamma[col];
    float4 bt = *(const float4*)&beta[col];

    // ---- batched loads: warp w owns edges base + w + 8*it, it = 0..3 ----
    int srcs[4], tgts[4];
#pragma unroll
    for (int it = 0; it < 4; it++) {
        int e = base + w + 8 * it;
        srcs[it] = __ldg(&eidx[e]);
        tgts[it] = __ldg(&eidx[EE + e]);
    }
    float2 pvi[4], pvj[4];
    float ai[4], aj[4];
    float4 Pi4[4], Pj4[4], ea4[4];
#pragma unroll
    for (int it = 0; it < 4; it++) {
        int e = base + w + 8 * it;
        pvi[it] = __ldg(&((const float2*)pos_i)[srcs[it]]);
        pvj[it] = __ldg(&((const float2*)pos_j)[tgts[it]]);
        ai[it] = __ldg(&hd_i[srcs[it]]);
        aj[it] = __ldg(&hd_j[tgts[it]]);
        Pi4[it] = __ldg((const float4*)&g_Pi[(size_t)srcs[it] * HH + col]);
        Pj4[it] = __ldg((const float4*)&g_Pj[(size_t)tgts[it] * HH + col]);
        ea4[it] = __ldg((const float4*)&edge_attr[(size_t)e * HH + col]);
    }

    // ---- compute all 4 edges from registers ----
#pragma unroll
    for (int it = 0; it < 4; it++) {
        int e = base + w + 8 * it;
        float dx = pvi[it].x - pvj[it].x;
        float dy = pvi[it].y - pvj[it].y;

        float sj, cj;
        __sincosf(aj[it], &sj, &cj);
        float x1 = dx * cj + dy * sj;
        float y1 = -dx * sj + dy * cj;
        float len1 = sqrtf(x1 * x1 + y1 * y1);
        float il1 = (len1 > 0.f) ? (1.f / len1) : 0.f;
        float ct1 = (len1 > 0.f) ? (x1 * il1) : 1.f;
        float st1 = y1 * il1;

        float si, ci;
        __sincosf(ai[it], &si, &ci);
        float x2 = -dx * ci - dy * si;
        float y2 = dx * si - dy * ci;
        float len2 = sqrtf(x2 * x2 + y2 * y2);
        float il2 = (len2 > 0.f) ? (1.f / len2) : 0.f;
        float ct2 = (len2 > 0.f) ? (x2 * il2) : 1.f;
        float st2 = y2 * il2;

        float shd, chd;
        __sincosf(ai[it] - aj[it], &shd, &chd);

        float raw[10];
        raw[0] = len1; raw[1] = ct1; raw[2] = st1; raw[3] = chd; raw[4] = shd;
        raw[5] = len2; raw[6] = ct2; raw[7] = st2; raw[8] = chd; raw[9] = -shd;

        float4 g = make_float4(0.f, 0.f, 0.f, 0.f);
#pragma unroll
        for (int d = 0; d < 10; d++) {
            float4 wc = *(const float4*)&sWc[d * HH + col];
            g.x = fmaf(raw[d], wc.x, g.x);
            g.y = fmaf(raw[d], wc.y, g.y);
            g.z = fmaf(raw[d], wc.z, g.z);
            g.w = fmaf(raw[d], wc.w, g.w);
        }
        g.x = fmaxf(g.x, 0.f); g.y = fmaxf(g.y, 0.f);
        g.z = fmaxf(g.z, 0.f); g.w = fmaxf(g.w, 0.f);

        float4 pre;
        pre.x = fmaf(g.x, sigmoidf_(Pi4[it].x + Pj4[it].x + bs.x), ea4[it].x);
        pre.y = fmaf(g.y, sigmoidf_(Pi4[it].y + Pj4[it].y + bs.y), ea4[it].y);
        pre.z = fmaf(g.z, sigmoidf_(Pi4[it].z + Pj4[it].z + bs.z), ea4[it].z);
        pre.w = fmaf(g.w, sigmoidf_(Pi4[it].w + Pj4[it].w + bs.w), ea4[it].w);

        float ssum = pre.x + pre.y + pre.z + pre.w;
#pragma unroll
        for (int off = 16; off >= 1; off >>= 1)
            ssum += __shfl_xor_sync(0xffffffffu, ssum, off);
        float mu = ssum * (1.0f / 128.0f);
        float4 dv;
        dv.x = pre.x - mu; dv.y = pre.y - mu;
        dv.z = pre.z - mu; dv.w = pre.w - mu;
        float sq = dv.x * dv.x + dv.y * dv.y + dv.z * dv.z + dv.w * dv.w;
#pragma unroll
        for (int off = 16; off >= 1; off >>= 1)
            sq += __shfl_xor_sync(0xffffffffu, sq, off);
        float rstd = rsqrtf(sq * (1.0f / 128.0f) + 1e-5f);

        float4 h4;
        h4.x = fmaf(dv.x * rstd, gm.x, bt.x);
        h4.y = fmaf(dv.y * rstd, gm.y, bt.y);
        h4.z = fmaf(dv.z * rstd, gm.z, bt.z);
        h4.w = fmaf(dv.w * rstd, gm.w, bt.w);

        size_t o = (size_t)e * HH + col;
        __half2 hh0 = __float22half2_rn(make_float2(h4.x, h4.y));
        __half2 hh1 = __float22half2_rn(make_float2(h4.z, h4.w));
        *(uint2*)&g_H16[o] = make_uint2(h2u(hh0), h2u(hh1));

        __half2 ee0 = __float22half2_rn(make_float2(ea4[it].x, ea4[it].y));
        __half2 ee1 = __float22half2_rn(make_float2(ea4[it].z, ea4[it].w));
        *(uint2*)&g_EA16[o] = make_uint2(h2u(ee0), h2u(ee1));
    }
}

// ---------------------------------------------------------------------------
// GEMM kernel: persistent CTAs, 512 threads. Per tile (128 edges):
// gate = h @ Wgate, res = ea @ Wres via fp16 m16n8k16 mma; fused epilogue.
// Epilogue h comes from the smem fp16 tile (no fp32 global round-trip).
// ---------------------------------------------------------------------------
__global__ __launch_bounds__(512, 1) void gemm_kernel(
    const float* __restrict__ Wgate, const float* __restrict__ Wres,
    float* __restrict__ out) {
    extern __shared__ char smc[];
    __half* sWg = (__half*)(smc + GOFF_WG);
    __half* sWr = (__half*)(smc + GOFF_WR);
    uint32_t sb = smem_u32(smc);

    int tid = threadIdx.x;
    int lane = tid & 31;
    int w = tid >> 5;
    int gid = lane >> 2;
    int tig = lane & 3;
    int mb = (w >> 2) * 32;
    int nb = (w & 3) * 32;

    // stage weights once: sW[n][k] (transposed), stride 136 halves
    for (int i = tid; i < 16384; i += 512) {
        int n = i & 127, k = i >> 7;
        sWg[n * 136 + k] = __float2half(Wgate[k * HH + n]);
        sWr[n * 136 + k] = __float2half(Wres[k * HH + n]);
    }

    const uint32_t bufH[2] = {sb + GOFF_B0H, sb + GOFF_B1H};
    const uint32_t bufE[2] = {sb + GOFF_B0E, sb + GOFF_B1E};

    int t = blockIdx.x;
    if (t >= NT) return;

    // prologue: stage first tile
    for (int c = tid; c < 2048; c += 512) {
        int r = c >> 4, cc = c & 15;
        long e = (long)t * 128 + r;
        if (e >= EE) e = EE - 1;
        CP_ASYNC_16(bufH[0] + r * 272 + cc * 16, (const void*)(g_H16 + e * HH + cc * 8));
        CP_ASYNC_16(bufE[0] + r * 272 + cc * 16, (const void*)(g_EA16 + e * HH + cc * 8));
    }
    CP_COMMIT();

    int cur = 0;
    while (t < NT) {
        int nxt = t + (int)gridDim.x;
        if (nxt < NT) {
            for (int c = tid; c < 2048; c += 512) {
                int r = c >> 4, cc = c & 15;
                long e = (long)nxt * 128 + r;
                if (e >= EE) e = EE - 1;
                CP_ASYNC_16(bufH[cur ^ 1] + r * 272 + cc * 16,
                            (const void*)(g_H16 + e * HH + cc * 8));
                CP_ASYNC_16(bufE[cur ^ 1] + r * 272 + cc * 16,
                            (const void*)(g_EA16 + e * HH + cc * 8));
            }
            CP_COMMIT();
            CP_WAIT(1);
        } else {
            CP_WAIT(0);
        }
        __syncthreads();

        const __half* sH = (const __half*)(smc + (bufH[cur] - sb));
        const __half* sE = (const __half*)(smc + (bufE[cur] - sb));

        float aG[2][4][4];
        float aR[2][4][4];
#pragma unroll
        for (int mt = 0; mt < 2; mt++)
#pragma unroll
            for (int nt = 0; nt < 4; nt++)
#pragma unroll
                for (int q = 0; q < 4; q++) { aG[mt][nt][q] = 0.f; aR[mt][nt][q] = 0.f; }

#pragma unroll
        for (int kt = 0; kt < 8; kt++) {
            int k0 = kt * 16;
            uint32_t bg[4][2], br[4][2];
#pragma unroll
            for (int nt = 0; nt < 4; nt++) {
                int n = nb + nt * 8 + gid;
                bg[nt][0] = *(const uint32_t*)&sWg[n * 136 + k0 + 2 * tig];
                bg[nt][1] = *(const uint32_t*)&sWg[n * 136 + k0 + 2 * tig + 8];
                br[nt][0] = *(const uint32_t*)&sWr[n * 136 + k0 + 2 * tig];
                br[nt][1] = *(const uint32_t*)&sWr[n * 136 + k0 + 2 * tig + 8];
            }
#pragma unroll
            for (int mt = 0; mt < 2; mt++) {
                int r0 = mb + mt * 16 + gid;
                uint32_t ha0 = *(const uint32_t*)&sH[r0 * 136 + k0 + 2 * tig];
                uint32_t ha1 = *(const uint32_t*)&sH[(r0 + 8) * 136 + k0 + 2 * tig];
                uint32_t ha2 = *(const uint32_t*)&sH[r0 * 136 + k0 + 2 * tig + 8];
                uint32_t ha3 = *(const uint32_t*)&sH[(r0 + 8) * 136 + k0 + 2 * tig + 8];
                uint32_t ea0 = *(const uint32_t*)&sE[r0 * 136 + k0 + 2 * tig];
                uint32_t ea1 = *(const uint32_t*)&sE[(r0 + 8) * 136 + k0 + 2 * tig];
                uint32_t ea2 = *(const uint32_t*)&sE[r0 * 136 + k0 + 2 * tig + 8];
                uint32_t ea3 = *(const uint32_t*)&sE[(r0 + 8) * 136 + k0 + 2 * tig + 8];
#pragma unroll
                for (int nt = 0; nt < 4; nt++) {
                    mma_f16(aG[mt][nt], ha0, ha1, ha2, ha3, bg[nt][0], bg[nt][1]);
                    mma_f16(aR[mt][nt], ea0, ea1, ea2, ea3, br[nt][0], br[nt][1]);
                }
            }
        }

        // epilogue: out = h + sigmoid(gate) * (res - h), h from smem fp16 tile
#pragma unroll
        for (int mt = 0; mt < 2; mt++) {
#pragma unroll
            for (int nt = 0; nt < 4; nt++) {
                int c0 = nb + nt * 8 + 2 * tig;
#pragma unroll
                for (int hf = 0; hf < 2; hf++) {
                    int r = mb + mt * 16 + gid + hf * 8;
                    long e = (long)t * 128 + r;
                    if (e < EE) {
                        float2 h2 = __half22float2(*(const __half2*)&sH[r * 136 + c0]);
                        float s0 = sigmoidf_(aG[mt][nt][hf * 2 + 0]);
                        float s1 = sigmoidf_(aG[mt][nt][hf * 2 + 1]);
                        float2 o;
                        o.x = fmaf(s0, aR[mt][nt][hf * 2 + 0] - h2.x, h2.x);
                        o.y = fmaf(s1, aR[mt][nt][hf * 2 + 1] - h2.y, h2.y);
                        *(float2*)&out[(size_t)e * HH + c0] = o;
                    }
                }
            }
        }
        __syncthreads();   // all warps done with buf[cur] before it is refilled
        cur ^= 1;
        t = nxt;
    }
}

// ---------------------------------------------------------------------------
extern "C" void kernel_launch(void* const* d_in, const int* in_sizes, int n_in,
                              void* d_out, int out_size) {
    const float* pos_i     = (const float*)d_in[0];
    const float* pos_j     = (const float*)d_in[1];
    const float* hd_i      = (const float*)d_in[2];
    const float* hd_j      = (const float*)d_in[3];
    const int*   eidx      = (const int*)d_in[4];
    const float* edge_attr = (const float*)d_in[5];
    const float* embs_i    = (const float*)d_in[6];
    const float* embs_j    = (const float*)d_in[7];
    const float* Wgeo      = (const float*)d_in[8];
    const float* Wpair     = (const float*)d_in[9];
    const float* Wsem      = (const float*)d_in[10];
    const float* bsem      = (const float*)d_in[11];
    const float* gamma     = (const float*)d_in[12];
    const float* beta      = (const float*)d_in[13];
    const float* Wgate     = (const float*)d_in[14];
    const float* Wres      = (const float*)d_in[15];

    const int smem_pk = (128 * SP * 2 + 64 * SP * 2) * 4;  // 202752

    cudaFuncSetAttribute(pk_kernel, cudaFuncAttributeMaxDynamicSharedMemorySize,
                         smem_pk);
    cudaFuncSetAttribute(gemm_kernel, cudaFuncAttributeMaxDynamicSharedMemorySize,
                         GSMEM);

    pk_kernel<<<148, 256, smem_pk>>>(embs_i, embs_j, Wsem, Wgeo, Wpair);
    phaseA_kernel<<<EE / 32, 256>>>(pos_i, pos_j, hd_i, hd_j, eidx, edge_attr,
                                    bsem, gamma, beta);
    gemm_kernel<<<148, 512, GSMEM>>>(Wgate, Wres, (float*)d_out);
}

// round 12
// speedup vs baseline: 1.1189x; 1.1189x over previous
#include <cuda_runtime.h>
#include <cuda_fp16.h>
#include <cstdint>
#include <cstring>
#include <math.h>

#define NN 50000
#define EE 600000
#define HH 128
#define SP 132          // pk kernel padded stride (floats)
#define NPT 782         // ceil(NN/64) node tiles
#define NT 4688         // ceil(EE/128) edge tiles
#define NAT 9375        // EE/64 phaseA tiles

// ---- gemm smem byte offsets ----
#define GOFF_WG   0          // 128*136 half = 34816
#define GOFF_WR   34816
#define GOFF_B0H  69632
#define GOFF_B0E  104448
#define GOFF_B1H  139264
#define GOFF_B1E  174080
#define GSMEM     208896

// Scratch (__device__ globals: alloc-free rule)
__device__ __align__(16) float  g_Pi[NN * HH];
__device__ __align__(16) float  g_Pj[NN * HH];
__device__ __align__(16) float  g_Wcomb[10 * HH];
__device__ __align__(16) __half g_H16[(size_t)EE * HH];
__device__ __align__(16) __half g_EA16[(size_t)EE * HH];

__device__ __forceinline__ float sigmoidf_(float x) {
    return 1.0f / (1.0f + __expf(-x));
}
__device__ __forceinline__ uint32_t h2u(__half2 v) {
    uint32_t r;
    memcpy(&r, &v, 4);
    return r;
}
__device__ __forceinline__ unsigned f2tf32(float x) {
    unsigned r;
    asm("cvt.rna.tf32.f32 %0, %1;" : "=r"(r) : "f"(x));
    return r;
}
__device__ __forceinline__ uint32_t smem_u32(const void* smem_ptr) {
    uint32_t addr;
    asm("{ .reg .u64 tmp; cvta.to.shared.u64 tmp, %1; cvt.u32.u64 %0, tmp; }"
        : "=r"(addr) : "l"(smem_ptr));
    return addr;
}
__device__ __forceinline__ void mma_tf32(float* d, unsigned a0, unsigned a1,
                                         unsigned a2, unsigned a3,
                                         unsigned b0, unsigned b1) {
    asm volatile(
        "mma.sync.aligned.m16n8k8.row.col.f32.tf32.tf32.f32 "
        "{%0,%1,%2,%3}, {%4,%5,%6,%7}, {%8,%9}, {%0,%1,%2,%3};\n"
        : "+f"(d[0]), "+f"(d[1]), "+f"(d[2]), "+f"(d[3])
        : "r"(a0), "r"(a1), "r"(a2), "r"(a3), "r"(b0), "r"(b1));
}
__device__ __forceinline__ void mma_f16(float* d, uint32_t a0, uint32_t a1,
                                        uint32_t a2, uint32_t a3,
                                        uint32_t b0, uint32_t b1) {
    asm volatile(
        "mma.sync.aligned.m16n8k16.row.col.f32.f16.f16.f32 "
        "{%0,%1,%2,%3}, {%4,%5,%6,%7}, {%8,%9}, {%0,%1,%2,%3};\n"
        : "+f"(d[0]), "+f"(d[1]), "+f"(d[2]), "+f"(d[3])
        : "r"(a0), "r"(a1), "r"(a2), "r"(a3), "r"(b0), "r"(b1));
}

#define CP_ASYNC_16(dst_u32, src_ptr) \
    asm volatile("cp.async.cg.shared.global [%0], [%1], 16;" \
                 :: "r"(dst_u32), "l"(src_ptr) : "memory")
#define CP_COMMIT() asm volatile("cp.async.commit_group;" ::: "memory")
#define CP_WAIT(n)  asm volatile("cp.async.wait_group %0;" :: "n"(n) : "memory")

// ---------------------------------------------------------------------------
// Setup kernel: wcomb (blocks 0-9) + P precompute (tf32 mma).
// PERSISTENT: 148 CTAs loop over node tiles; weights staged once per CTA.
// ---------------------------------------------------------------------------
__global__ __launch_bounds__(256, 1) void pk_kernel(const float* __restrict__ Ei,
                                                    const float* __restrict__ Ej,
                                                    const float* __restrict__ Wsem,
                                                    const float* __restrict__ Wgeo,
                                                    const float* __restrict__ Wpair) {
    extern __shared__ float sm[];
    float* sWt = sm;
    float* sWb = sWt + 128 * SP;
    float* sAi = sWb + 128 * SP;
    float* sAj = sAi + 64 * SP;

    int tid = threadIdx.x;
    int lane = tid & 31;
    int w = tid >> 5;

    if (blockIdx.x < 10 && tid < 128) {
        int c = tid;
        int d = blockIdx.x;
        int dd = d % 5;
        const float* wp = Wpair + (d / 5) * 128 * HH;
        float acc = 0.0f;
#pragma unroll 16
        for (int m = 0; m < 128; m++)
            acc = fmaf(Wgeo[dd * HH + m], wp[m * HH + c], acc);
        g_Wcomb[d * HH + c] = acc;
    }

    // stage weights once per CTA
    for (int i = tid; i < 4096; i += 256) {
        int k = i >> 5, c4 = i & 31;
        float4 t = ((const float4*)Wsem)[i];
        float4 b = ((const float4*)(Wsem + 128 * HH))[i];
        *(uint4*)&sWt[k * SP + c4 * 4] =
            make_uint4(f2tf32(t.x), f2tf32(t.y), f2tf32(t.z), f2tf32(t.w));
        *(uint4*)&sWb[k * SP + c4 * 4] =
            make_uint4(f2tf32(b.x), f2tf32(b.y), f2tf32(b.z), f2tf32(b.w));
    }

    const float* A = (w < 4) ? sAi : sAj;
    const float* W = (w < 4) ? sWt : sWb;
    int nb = (w & 3) * 32;
    int gid = lane >> 2, tig = lane & 3;

    for (int t = blockIdx.x; t < NPT; t += (int)gridDim.x) {
        int base = t * 64;
        __syncthreads();   // prior iteration's sA reads done before overwrite
        for (int i = tid; i < 2048; i += 256) {
            int r = i >> 5, c4 = i & 31;
            int row = base + r;
            float4 v = make_float4(0.f, 0.f, 0.f, 0.f);
            float4 u = make_float4(0.f, 0.f, 0.f, 0.f);
            if (row < NN) {
                v = ((const float4*)Ei)[row * 32 + c4];
                u = ((const float4*)Ej)[row * 32 + c4];
            }
            *(uint4*)&sAi[r * SP + c4 * 4] =
                make_uint4(f2tf32(v.x), f2tf32(v.y), f2tf32(v.z), f2tf32(v.w));
            *(uint4*)&sAj[r * SP + c4 * 4] =
                make_uint4(f2tf32(u.x), f2tf32(u.y), f2tf32(u.z), f2tf32(u.w));
        }
        __syncthreads();

        float acc[4][4][4];
#pragma unroll
        for (int mt = 0; mt < 4; mt++)
#pragma unroll
            for (int nt = 0; nt < 4; nt++)
#pragma unroll
                for (int q = 0; q < 4; q++) { acc[mt][nt][q] = 0.f; }

#pragma unroll
        for (int kt = 0; kt < 16; kt++) {
            int k0 = kt * 8;
            unsigned b[4][2];
#pragma unroll
            for (int nt = 0; nt < 4; nt++) {
                int n = nb + nt * 8 + gid;
                b[nt][0] = __float_as_uint(W[(k0 + tig) * SP + n]);
                b[nt][1] = __float_as_uint(W[(k0 + 4 + tig) * SP + n]);
            }
#pragma unroll
            for (int mt = 0; mt < 4; mt++) {
                int m = mt * 16;
                unsigned a0 = __float_as_uint(A[(m + gid) * SP + k0 + tig]);
                unsigned a1 = __float_as_uint(A[(m + gid + 8) * SP + k0 + tig]);
                unsigned a2 = __float_as_uint(A[(m + gid) * SP + k0 + tig + 4]);
                unsigned a3 = __float_as_uint(A[(m + gid + 8) * SP + k0 + tig + 4]);
#pragma unroll
                for (int nt = 0; nt < 4; nt++)
                    mma_tf32(acc[mt][nt], a0, a1, a2, a3, b[nt][0], b[nt][1]);
            }
        }

        float* G = (w < 4) ? g_Pi : g_Pj;
#pragma unroll
        for (int mt = 0; mt < 4; mt++)
#pragma unroll
            for (int nt = 0; nt < 4; nt++) {
                int row0 = base + mt * 16 + gid;
                int col = nb + nt * 8 + 2 * tig;
                if (row0 < NN)
                    *(float2*)&G[(size_t)row0 * HH + col] =
                        make_float2(acc[mt][nt][0], acc[mt][nt][1]);
                int row1 = row0 + 8;
                if (row1 < NN)
                    *(float2*)&G[(size_t)row1 * HH + col] =
                        make_float2(acc[mt][nt][2], acc[mt][nt][3]);
            }
    }
}

// ---------------------------------------------------------------------------
// Phase A kernel: geometry + gate + LayerNorm. PERSISTENT: 296 CTAs of 512
// threads grid-stride over 64-edge tiles. Weight table staged once per CTA.
// Body identical to the proven R10 version (same arithmetic order).
// ---------------------------------------------------------------------------
__global__ __launch_bounds__(512, 2) void phaseA_kernel(
    const float* __restrict__ pos_i, const float* __restrict__ pos_j,
    const float* __restrict__ hd_i, const float* __restrict__ hd_j,
    const int* __restrict__ eidx, const float* __restrict__ edge_attr,
    const float* __restrict__ b_sem, const float* __restrict__ gamma,
    const float* __restrict__ beta) {
    __shared__ float sWc[10 * HH];

    int tid = threadIdx.x;
    int lane = tid & 31;
    int w = tid >> 5;
    int col = lane * 4;

    for (int i = tid; i < 1280; i += 512) sWc[i] = g_Wcomb[i];
    __syncthreads();

    float4 bs = *(const float4*)&b_sem[col];
    float4 gm = *(const float4*)&gamma[col];
    float4 bt = *(const float4*)&beta[col];

    for (int t = blockIdx.x; t < NAT; t += (int)gridDim.x) {
        int base = t * 64;
#pragma unroll 2
        for (int it = 0; it < 4; it++) {
            int e = base + w + 16 * it;
            int src = __ldg(&eidx[e]);
            int tgt = __ldg(&eidx[EE + e]);

            float2 pvi = __ldg(&((const float2*)pos_i)[src]);
            float2 pvj = __ldg(&((const float2*)pos_j)[tgt]);
            float ang_i = __ldg(&hd_i[src]);
            float ang_j = __ldg(&hd_j[tgt]);
            float dx = pvi.x - pvj.x;
            float dy = pvi.y - pvj.y;

            float sj, cj;
            __sincosf(ang_j, &sj, &cj);
            float x1 = dx * cj + dy * sj;
            float y1 = -dx * sj + dy * cj;
            float len1 = sqrtf(x1 * x1 + y1 * y1);
            float il1 = (len1 > 0.f) ? (1.f / len1) : 0.f;
            float ct1 = (len1 > 0.f) ? (x1 * il1) : 1.f;
            float st1 = y1 * il1;

            float si, ci;
            __sincosf(ang_i, &si, &ci);
            float x2 = -dx * ci - dy * si;
            float y2 = dx * si - dy * ci;
            float len2 = sqrtf(x2 * x2 + y2 * y2);
            float il2 = (len2 > 0.f) ? (1.f / len2) : 0.f;
            float ct2 = (len2 > 0.f) ? (x2 * il2) : 1.f;
            float st2 = y2 * il2;

            float shd, chd;
            __sincosf(ang_i - ang_j, &shd, &chd);

            float raw[10];
            raw[0] = len1; raw[1] = ct1; raw[2] = st1; raw[3] = chd; raw[4] = shd;
            raw[5] = len2; raw[6] = ct2; raw[7] = st2; raw[8] = chd; raw[9] = -shd;

            float4 g = make_float4(0.f, 0.f, 0.f, 0.f);
#pragma unroll
            for (int d = 0; d < 10; d++) {
                float4 wc = *(const float4*)&sWc[d * HH + col];
                g.x = fmaf(raw[d], wc.x, g.x);
                g.y = fmaf(raw[d], wc.y, g.y);
                g.z = fmaf(raw[d], wc.z, g.z);
                g.w = fmaf(raw[d], wc.w, g.w);
            }
            g.x = fmaxf(g.x, 0.f); g.y = fmaxf(g.y, 0.f);
            g.z = fmaxf(g.z, 0.f); g.w = fmaxf(g.w, 0.f);

            float4 Pi4 = __ldg((const float4*)&g_Pi[(size_t)src * HH + col]);
            float4 Pj4 = __ldg((const float4*)&g_Pj[(size_t)tgt * HH + col]);
            float4 ea4 = __ldg((const float4*)&edge_attr[(size_t)e * HH + col]);

            float4 pre;
            pre.x = fmaf(g.x, sigmoidf_(Pi4.x + Pj4.x + bs.x), ea4.x);
            pre.y = fmaf(g.y, sigmoidf_(Pi4.y + Pj4.y + bs.y), ea4.y);
            pre.z = fmaf(g.z, sigmoidf_(Pi4.z + Pj4.z + bs.z), ea4.z);
            pre.w = fmaf(g.w, sigmoidf_(Pi4.w + Pj4.w + bs.w), ea4.w);

            float ssum = pre.x + pre.y + pre.z + pre.w;
#pragma unroll
            for (int off = 16; off >= 1; off >>= 1)
                ssum += __shfl_xor_sync(0xffffffffu, ssum, off);
            float mu = ssum * (1.0f / 128.0f);
            float4 dv;
            dv.x = pre.x - mu; dv.y = pre.y - mu;
            dv.z = pre.z - mu; dv.w = pre.w - mu;
            float sq = dv.x * dv.x + dv.y * dv.y + dv.z * dv.z + dv.w * dv.w;
#pragma unroll
            for (int off = 16; off >= 1; off >>= 1)
                sq += __shfl_xor_sync(0xffffffffu, sq, off);
            float rstd = rsqrtf(sq * (1.0f / 128.0f) + 1e-5f);

            float4 h4;
            h4.x = fmaf(dv.x * rstd, gm.x, bt.x);
            h4.y = fmaf(dv.y * rstd, gm.y, bt.y);
            h4.z = fmaf(dv.z * rstd, gm.z, bt.z);
            h4.w = fmaf(dv.w * rstd, gm.w, bt.w);

            size_t o = (size_t)e * HH + col;
            __half2 hh0 = __float22half2_rn(make_float2(h4.x, h4.y));
            __half2 hh1 = __float22half2_rn(make_float2(h4.z, h4.w));
            *(uint2*)&g_H16[o] = make_uint2(h2u(hh0), h2u(hh1));

            __half2 ee0 = __float22half2_rn(make_float2(ea4.x, ea4.y));
            __half2 ee1 = __float22half2_rn(make_float2(ea4.z, ea4.w));
            *(uint2*)&g_EA16[o] = make_uint2(h2u(ee0), h2u(ee1));
        }
    }
}

// ---------------------------------------------------------------------------
// GEMM kernel: persistent CTAs, 512 threads. Per tile (128 edges):
// gate = h @ Wgate, res = ea @ Wres via fp16 m16n8k16 mma; fused epilogue.
// Epilogue h comes from the smem fp16 tile (no fp32 global round-trip).
// ---------------------------------------------------------------------------
__global__ __launch_bounds__(512, 1) void gemm_kernel(
    const float* __restrict__ Wgate, const float* __restrict__ Wres,
    float* __restrict__ out) {
    extern __shared__ char smc[];
    __half* sWg = (__half*)(smc + GOFF_WG);
    __half* sWr = (__half*)(smc + GOFF_WR);
    uint32_t sb = smem_u32(smc);

    int tid = threadIdx.x;
    int lane = tid & 31;
    int w = tid >> 5;
    int gid = lane >> 2;
    int tig = lane & 3;
    int mb = (w >> 2) * 32;
    int nb = (w & 3) * 32;

    // stage weights once: sW[n][k] (transposed), stride 136 halves
    for (int i = tid; i < 16384; i += 512) {
        int n = i & 127, k = i >> 7;
        sWg[n * 136 + k] = __float2half(Wgate[k * HH + n]);
        sWr[n * 136 + k] = __float2half(Wres[k * HH + n]);
    }

    const uint32_t bufH[2] = {sb + GOFF_B0H, sb + GOFF_B1H};
    const uint32_t bufE[2] = {sb + GOFF_B0E, sb + GOFF_B1E};

    int t = blockIdx.x;
    if (t >= NT) return;

    // prologue: stage first tile
    for (int c = tid; c < 2048; c += 512) {
        int r = c >> 4, cc = c & 15;
        long e = (long)t * 128 + r;
        if (e >= EE) e = EE - 1;
        CP_ASYNC_16(bufH[0] + r * 272 + cc * 16, (const void*)(g_H16 + e * HH + cc * 8));
        CP_ASYNC_16(bufE[0] + r * 272 + cc * 16, (const void*)(g_EA16 + e * HH + cc * 8));
    }
    CP_COMMIT();

    int cur = 0;
    while (t < NT) {
        int nxt = t + (int)gridDim.x;
        if (nxt < NT) {
            for (int c = tid; c < 2048; c += 512) {
                int r = c >> 4, cc = c & 15;
                long e = (long)nxt * 128 + r;
                if (e >= EE) e = EE - 1;
                CP_ASYNC_16(bufH[cur ^ 1] + r * 272 + cc * 16,
                            (const void*)(g_H16 + e * HH + cc * 8));
                CP_ASYNC_16(bufE[cur ^ 1] + r * 272 + cc * 16,
                            (const void*)(g_EA16 + e * HH + cc * 8));
            }
            CP_COMMIT();
            CP_WAIT(1);
        } else {
            CP_WAIT(0);
        }
        __syncthreads();

        const __half* sH = (const __half*)(smc + (bufH[cur] - sb));
        const __half* sE = (const __half*)(smc + (bufE[cur] - sb));

        float aG[2][4][4];
        float aR[2][4][4];
#pragma unroll
        for (int mt = 0; mt < 2; mt++)
#pragma unroll
            for (int nt = 0; nt < 4; nt++)
#pragma unroll
                for (int q = 0; q < 4; q++) { aG[mt][nt][q] = 0.f; aR[mt][nt][q] = 0.f; }

#pragma unroll
        for (int kt = 0; kt < 8; kt++) {
            int k0 = kt * 16;
            uint32_t bg[4][2], br[4][2];
#pragma unroll
            for (int nt = 0; nt < 4; nt++) {
                int n = nb + nt * 8 + gid;
                bg[nt][0] = *(const uint32_t*)&sWg[n * 136 + k0 + 2 * tig];
                bg[nt][1] = *(const uint32_t*)&sWg[n * 136 + k0 + 2 * tig + 8];
                br[nt][0] = *(const uint32_t*)&sWr[n * 136 + k0 + 2 * tig];
                br[nt][1] = *(const uint32_t*)&sWr[n * 136 + k0 + 2 * tig + 8];
            }
#pragma unroll
            for (int mt = 0; mt < 2; mt++) {
                int r0 = mb + mt * 16 + gid;
                uint32_t ha0 = *(const uint32_t*)&sH[r0 * 136 + k0 + 2 * tig];
                uint32_t ha1 = *(const uint32_t*)&sH[(r0 + 8) * 136 + k0 + 2 * tig];
                uint32_t ha2 = *(const uint32_t*)&sH[r0 * 136 + k0 + 2 * tig + 8];
                uint32_t ha3 = *(const uint32_t*)&sH[(r0 + 8) * 136 + k0 + 2 * tig + 8];
                uint32_t ea0 = *(const uint32_t*)&sE[r0 * 136 + k0 + 2 * tig];
                uint32_t ea1 = *(const uint32_t*)&sE[(r0 + 8) * 136 + k0 + 2 * tig];
                uint32_t ea2 = *(const uint32_t*)&sE[r0 * 136 + k0 + 2 * tig + 8];
                uint32_t ea3 = *(const uint32_t*)&sE[(r0 + 8) * 136 + k0 + 2 * tig + 8];
#pragma unroll
                for (int nt = 0; nt < 4; nt++) {
                    mma_f16(aG[mt][nt], ha0, ha1, ha2, ha3, bg[nt][0], bg[nt][1]);
                    mma_f16(aR[mt][nt], ea0, ea1, ea2, ea3, br[nt][0], br[nt][1]);
                }
            }
        }

        // epilogue: out = h + sigmoid(gate) * (res - h), h from smem fp16 tile
#pragma unroll
        for (int mt = 0; mt < 2; mt++) {
#pragma unroll
            for (int nt = 0; nt < 4; nt++) {
                int c0 = nb + nt * 8 + 2 * tig;
#pragma unroll
                for (int hf = 0; hf < 2; hf++) {
                    int r = mb + mt * 16 + gid + hf * 8;
                    long e = (long)t * 128 + r;
                    if (e < EE) {
                        float2 h2 = __half22float2(*(const __half2*)&sH[r * 136 + c0]);
                        float s0 = sigmoidf_(aG[mt][nt][hf * 2 + 0]);
                        float s1 = sigmoidf_(aG[mt][nt][hf * 2 + 1]);
                        float2 o;
                        o.x = fmaf(s0, aR[mt][nt][hf * 2 + 0] - h2.x, h2.x);
                        o.y = fmaf(s1, aR[mt][nt][hf * 2 + 1] - h2.y, h2.y);
                        *(float2*)&out[(size_t)e * HH + c0] = o;
                    }
                }
            }
        }
        __syncthreads();   // all warps done with buf[cur] before it is refilled
        cur ^= 1;
        t = nxt;
    }
}

// ---------------------------------------------------------------------------
extern "C" void kernel_launch(void* const* d_in, const int* in_sizes, int n_in,
                              void* d_out, int out_size) {
    const float* pos_i     = (const float*)d_in[0];
    const float* pos_j     = (const float*)d_in[1];
    const float* hd_i      = (const float*)d_in[2];
    const float* hd_j      = (const float*)d_in[3];
    const int*   eidx      = (const int*)d_in[4];
    const float* edge_attr = (const float*)d_in[5];
    const float* embs_i    = (const float*)d_in[6];
    const float* embs_j    = (const float*)d_in[7];
    const float* Wgeo      = (const float*)d_in[8];
    const float* Wpair     = (const float*)d_in[9];
    const float* Wsem      = (const float*)d_in[10];
    const float* bsem      = (const float*)d_in[11];
    const float* gamma     = (const float*)d_in[12];
    const float* beta      = (const float*)d_in[13];
    const float* Wgate     = (const float*)d_in[14];
    const float* Wres      = (const float*)d_in[15];

    const int smem_pk = (128 * SP * 2 + 64 * SP * 2) * 4;  // 202752

    cudaFuncSetAttribute(pk_kernel, cudaFuncAttributeMaxDynamicSharedMemorySize,
                         smem_pk);
    cudaFuncSetAttribute(gemm_kernel, cudaFuncAttributeMaxDynamicSharedMemorySize,
                         GSMEM);

    pk_kernel<<<148, 256, smem_pk>>>(embs_i, embs_j, Wsem, Wgeo, Wpair);
    phaseA_kernel<<<296, 512>>>(pos_i, pos_j, hd_i, hd_j, eidx, edge_attr,
                                bsem, gamma, beta);
    gemm_kernel<<<148, 512, GSMEM>>>(Wgate, Wres, (float*)d_out);
}